// round 4
// baseline (speedup 1.0000x reference)
#include <cuda_runtime.h>
#include <climits>

#define NB 32
#define H 512
#define W 512
#define C 3
#define OUT 400
#define THRESH 0.7f

#define BPB 16                      // bounds blocks per batch
#define ROWS_PER_BLK (H / BPB)      // 32
#define TB 256

// Per-block partial bbox: rmin, rmax, cmin, cmax. Plain-stored every launch,
// so no init kernel / no atomics / no cross-replay state.
__device__ int g_part[NB * BPB][4];

__global__ void bounds_kernel(const float* __restrict__ tensor) {
    int blk  = blockIdx.x;
    int b    = blk / BPB;
    int rb   = blk % BPB;
    int row0 = rb * ROWS_PER_BLK;

    const float4* base =
        (const float4*)(tensor + ((size_t)b * H + row0) * W);

    int rmin = INT_MAX, rmax = -1, cmin = INT_MAX, cmax = -1;

    const int NV = ROWS_PER_BLK * (W / 4);  // 32 * 128 = 4096 float4s
    for (int j = threadIdx.x; j < NV; j += TB) {
        float4 v = base[j];
        int r = j >> 7;            // j / 128
        int c = (j & 127) << 2;    // (j % 128) * 4
        bool any = false;
        if (v.x > THRESH) { any = true; cmin = min(cmin, c    ); cmax = max(cmax, c    ); }
        if (v.y > THRESH) { any = true; cmin = min(cmin, c + 1); cmax = max(cmax, c + 1); }
        if (v.z > THRESH) { any = true; cmin = min(cmin, c + 2); cmax = max(cmax, c + 2); }
        if (v.w > THRESH) { any = true; cmin = min(cmin, c + 3); cmax = max(cmax, c + 3); }
        if (any) {
            int rr = row0 + r;
            rmin = min(rmin, rr);
            rmax = max(rmax, rr);
        }
    }

    #pragma unroll
    for (int o = 16; o > 0; o >>= 1) {
        rmin = min(rmin, __shfl_xor_sync(0xFFFFFFFFu, rmin, o));
        rmax = max(rmax, __shfl_xor_sync(0xFFFFFFFFu, rmax, o));
        cmin = min(cmin, __shfl_xor_sync(0xFFFFFFFFu, cmin, o));
        cmax = max(cmax, __shfl_xor_sync(0xFFFFFFFFu, cmax, o));
    }

    __shared__ int s[4][TB / 32];
    int wid = threadIdx.x >> 5, lid = threadIdx.x & 31;
    if (lid == 0) { s[0][wid] = rmin; s[1][wid] = rmax; s[2][wid] = cmin; s[3][wid] = cmax; }
    __syncthreads();
    if (threadIdx.x == 0) {
        #pragma unroll
        for (int i = 1; i < TB / 32; i++) {
            rmin = min(rmin, s[0][i]); rmax = max(rmax, s[1][i]);
            cmin = min(cmin, s[2][i]); cmax = max(cmax, s[3][i]);
        }
        g_part[blk][0] = rmin;
        g_part[blk][1] = rmax;
        g_part[blk][2] = cmin;
        g_part[blk][3] = cmax;
    }
}

// Inline replica of _axis_coords (float32 op order preserved).
// Handles the all-False-mask case: jnp.argmax on all-False gives (0, n-1).
__device__ __forceinline__ void axis_coords(int lo, int hi, int i,
                                            int& i0g, int& i1g, float& w) {
    if (hi < lo) { lo = 0; hi = H - 1; }   // H == W == 512
    float size = (float)(hi - lo);
    float src  = ((float)i + 0.5f) * size / (float)OUT - 0.5f;
    float mx   = fmaxf(size - 1.0f, 0.0f);
    src = fminf(fmaxf(src, 0.0f), mx);
    int   i0 = (int)floorf(src);
    int   i1 = min(i0 + 1, max(hi - lo - 1, 0));
    w = src - (float)i0;
    i0g = lo + i0;
    i1g = lo + i1;
}

#define RT 128   // threads per resize block

// One block per (batch, output row). Warp 0 reduces this batch's 16 bbox
// partials; two input rows staged to smem with coalesced float4 loads;
// bilinear gather from smem; output row staged to smem, written as float4.
__global__ __launch_bounds__(RT) void resize_kernel(const float* __restrict__ img,
                                                    float* __restrict__ out) {
    int blk = blockIdx.x;          // b * OUT + r
    int b   = blk / OUT;
    int r   = blk - b * OUT;

    __shared__ float row0[W * C];      // 6 KB
    __shared__ float row1[W * C];      // 6 KB
    __shared__ float obuf[OUT * C];    // 4.8 KB
    __shared__ int   sb[4];

    // Reduce the 16 per-block partials for this batch (warp 0).
    if (threadIdx.x < 32) {
        int rmin = INT_MAX, rmax = -1, cmin = INT_MAX, cmax = -1;
        if (threadIdx.x < BPB) {
            const int* p = g_part[b * BPB + threadIdx.x];
            rmin = p[0]; rmax = p[1]; cmin = p[2]; cmax = p[3];
        }
        #pragma unroll
        for (int o = 8; o > 0; o >>= 1) {
            rmin = min(rmin, __shfl_xor_sync(0xFFFFFFFFu, rmin, o));
            rmax = max(rmax, __shfl_xor_sync(0xFFFFFFFFu, rmax, o));
            cmin = min(cmin, __shfl_xor_sync(0xFFFFFFFFu, cmin, o));
            cmax = max(cmax, __shfl_xor_sync(0xFFFFFFFFu, cmax, o));
        }
        if (threadIdx.x == 0) {
            sb[0] = rmin; sb[1] = rmax; sb[2] = cmin; sb[3] = cmax;
        }
    }
    __syncthreads();

    int rlo = sb[0], rhi = sb[1], clo = sb[2], chi = sb[3];

    int r0, r1; float wr;
    axis_coords(rlo, rhi, r, r0, r1, wr);

    const float4* s0 = (const float4*)(img + ((size_t)b * H + r0) * W * C);
    const float4* s1 = (const float4*)(img + ((size_t)b * H + r1) * W * C);
    float4* d0 = (float4*)row0;
    float4* d1 = (float4*)row1;
    #pragma unroll
    for (int it = 0; it < (W * C / 4) / RT; it++) {   // 384/128 = 3 exact
        int j = it * RT + threadIdx.x;
        d0[j] = s0[j];
        d1[j] = s1[j];
    }
    __syncthreads();

    float omwr = 1.0f - wr;

    for (int c = threadIdx.x; c < OUT; c += RT) {
        int c0, c1; float wc;
        axis_coords(clo, chi, c, c0, c1, wc);
        float omwc = 1.0f - wc;

        int o00 = c0 * C, o01 = c1 * C;
        float* o = obuf + c * C;
        #pragma unroll
        for (int ch = 0; ch < C; ch++) {
            float a00 = row0[o00 + ch];
            float a01 = row0[o01 + ch];
            float a10 = row1[o00 + ch];
            float a11 = row1[o01 + ch];
            float topv = a00 * omwc + a01 * wc;
            float botv = a10 * omwc + a11 * wc;
            o[ch] = topv * omwr + botv * wr;
        }
    }
    __syncthreads();

    // Coalesced float4 writeback: 1200 floats = 300 float4s.
    float4* orow = (float4*)(out + (size_t)blk * OUT * C);
    const float4* ob = (const float4*)obuf;
    for (int j = threadIdx.x; j < (OUT * C) / 4; j += RT) {
        orow[j] = ob[j];
    }
}

extern "C" void kernel_launch(void* const* d_in, const int* in_sizes, int n_in,
                              void* d_out, int out_size) {
    // Input-order detection: image has 25,165,824 elems, tensor 8,388,608.
    const float* image  = (const float*)d_in[0];
    const float* tensor = (const float*)d_in[1];
    if (n_in >= 2 && in_sizes[0] < in_sizes[1]) {
        image  = (const float*)d_in[1];
        tensor = (const float*)d_in[0];
    }
    float* out = (float*)d_out;

    bounds_kernel<<<NB * BPB, TB>>>(tensor);
    resize_kernel<<<NB * OUT, RT>>>(image, out);
}